// round 16
// baseline (speedup 1.0000x reference)
#include <cuda_runtime.h>
#include <cstddef>

#define NF 510
#define BB 32
#define HH 4
#define DD 64

// ---------------- scratch (__device__ globals; no allocation allowed) ----------------
__device__ float  g_xt[(size_t)BB*NF*256];        // xt[b][n][h*64+d]
__device__ float  g_si[BB*HH*NF];                 // s_i[b][h][n]
__device__ float  g_sj[BB*HH*NF];                 // s_j[b][h][n]
__device__ float4 g_cc[(size_t)NF*NF];            // 0.9*(conv3x3(causal, w[:,1]) + bias)
__device__ float  g_outp[4][(size_t)BB*NF*DD];    // per-head partial A_h @ xt_h

// ---- packed f32x2 helpers (FFMA2: 2 MACs / instruction) ----
__device__ __forceinline__ unsigned long long pk2(float v) {
    unsigned long long r;
    unsigned u = __float_as_uint(v);
    asm("mov.b64 %0, {%1, %1};" : "=l"(r) : "r"(u));
    return r;
}
__device__ __forceinline__ void ffma2(unsigned long long& d, unsigned long long a, unsigned long long b) {
    asm("fma.rn.f32x2 %0, %1, %2, %0;" : "+l"(d) : "l"(a), "l"(b));
}

// ---------------- K1: xt = x @ W   (16320x64 @ 64x256) ----------------
__global__ __launch_bounds__(256) void k_xt(const float* __restrict__ x,
                                            const float* __restrict__ W) {
    __shared__ __align__(16) float xs[16][64];
    int c = threadIdx.x;
    size_t base = (size_t)blockIdx.x * (16 * 64);
#pragma unroll
    for (int i = 0; i < 4; i++) {
        int idx = c + i * 256;
        xs[idx >> 6][idx & 63] = x[base + idx];
    }
    __syncthreads();
    float acc[16];
#pragma unroll
    for (int r = 0; r < 16; r++) acc[r] = 0.f;
    for (int kc = 0; kc < 16; kc++) {
        float w0 = W[(kc * 4 + 0) * 256 + c];
        float w1 = W[(kc * 4 + 1) * 256 + c];
        float w2 = W[(kc * 4 + 2) * 256 + c];
        float w3 = W[(kc * 4 + 3) * 256 + c];
#pragma unroll
        for (int r = 0; r < 16; r++) {
            float4 xv = *(const float4*)&xs[r][kc * 4];
            acc[r] = fmaf(xv.x, w0, acc[r]);
            acc[r] = fmaf(xv.y, w1, acc[r]);
            acc[r] = fmaf(xv.z, w2, acc[r]);
            acc[r] = fmaf(xv.w, w3, acc[r]);
        }
    }
    size_t ob = (size_t)blockIdx.x * (16 * 256);
#pragma unroll
    for (int r = 0; r < 16; r++) g_xt[ob + r * 256 + c] = acc[r];
}

// ---------------- K2: s_i, s_j (one warp per (b,n) row) ----------------
__global__ __launch_bounds__(256) void k_s(const float* __restrict__ attw) {
    __shared__ float aw[512];
    int tid = threadIdx.x;
    aw[tid] = attw[tid];
    aw[tid + 256] = attw[tid + 256];
    __syncthreads();
    int w = tid >> 5, lane = tid & 31;
    int row = blockIdx.x * 8 + w;
    const float* xr = g_xt + (size_t)row * 256;
    float xv[8];
#pragma unroll
    for (int j = 0; j < 8; j++) xv[j] = xr[lane + 32 * j];
    int b = row / NF, n = row % NF;
#pragma unroll
    for (int h = 0; h < 4; h++) {
        float si = xv[2*h] * aw[h*128 + lane] + xv[2*h+1] * aw[h*128 + 32 + lane];
        float sj = xv[2*h] * aw[h*128 + 64 + lane] + xv[2*h+1] * aw[h*128 + 96 + lane];
#pragma unroll
        for (int o = 16; o; o >>= 1) {
            si += __shfl_xor_sync(0xffffffffu, si, o);
            sj += __shfl_xor_sync(0xffffffffu, sj, o);
        }
        if (!lane) {
            g_si[(b * 4 + h) * NF + n] = si;
            g_sj[(b * 4 + h) * NF + n] = sj;
        }
    }
}

// ---------------- K2b: Cc = 0.9*(conv3x3(causal, w[:,1,:,:]) + bias), batch-invariant ----------------
__global__ __launch_bounds__(512) void k_cc(const float* __restrict__ causal,
                                            const float* __restrict__ cw,
                                            const float* __restrict__ cb) {
    __shared__ float cs[3][512];
    __shared__ float w1s[36];
    __shared__ float cbs[4];
    int m = threadIdx.x, n = blockIdx.x;
    if (m < 36) w1s[m] = 0.9f * cw[(m / 9) * 18 + 9 + (m % 9)];
    if (m < 4)  cbs[m] = 0.9f * cb[m];
#pragma unroll
    for (int ky = 0; ky < 3; ky++) {
        int rr = n + ky - 1;
        if (m < NF) cs[ky][m + 1] = (rr >= 0 && rr < NF) ? causal[rr * NF + m] : 0.f;
        else        cs[ky][m == NF ? 0 : 511] = 0.f;
    }
    __syncthreads();
    if (m < NF) {
        float c[9];
#pragma unroll
        for (int ky = 0; ky < 3; ky++)
#pragma unroll
            for (int kx = 0; kx < 3; kx++) c[ky * 3 + kx] = cs[ky][m + kx];
        float o[4];
#pragma unroll
        for (int h = 0; h < 4; h++) {
            float v = cbs[h];
#pragma unroll
            for (int j = 0; j < 9; j++) v = fmaf(w1s[h * 9 + j], c[j], v);
            o[h] = v;
        }
        g_cc[n * NF + m] = make_float4(o[0], o[1], o[2], o[3]);
    }
}

// ---------------- K3: warp-pair-per-row, 4 consecutive cols/lane (vector LDS taps) ----------------
// block = 512 thr = 16 warps = 8 rows x 2 head-slots; A written once from registers.
__global__ __launch_bounds__(512, 2) void k_attn(const float* __restrict__ cw,
                                                 float* __restrict__ Aout) {
    __shared__ __align__(16) float amean[10][520];   // conv input rows r0-1..r0+8; col = m+1
    __shared__ __align__(16) float sjs[4][512];      // s_j per head (cols 510,511 = 0)
    __shared__ float sis[10][4];                      // s_i rows r0-1 .. r0+8
    __shared__ float w0s[36];

    int tid = threadIdx.x;
    int b = blockIdx.y;
    int r0 = blockIdx.x * 8;
    int wid = tid >> 5, lane = tid & 31;
    int rt = wid >> 1;                 // row in tile 0..7
    int slot = wid & 1;                // head pair

#pragma unroll
    for (int h = 0; h < 4; h++)
        sjs[h][tid] = (tid < NF) ? g_sj[(b * 4 + h) * NF + tid] : 0.f;
    if (tid < 40) {
        int rr = tid >> 2, h = tid & 3;
        int row = r0 - 1 + rr;
        sis[rr][h] = ((unsigned)row < NF) ? g_si[(b * 4 + h) * NF + row] : 0.f;
    }
    if (tid < 36) w0s[tid] = 0.225f * cw[(tid / 9) * 18 + (tid % 9)];  // 0.9*0.25 folded
    __syncthreads();

    {
        float sjl[4];
#pragma unroll
        for (int h = 0; h < 4; h++) sjl[h] = sjs[h][tid];
        bool mok = tid < NF;
#pragma unroll
        for (int rr = 0; rr < 10; rr++) {
            int row = r0 - 1 + rr;
            float v = 0.f;
            if (mok && (unsigned)row < NF) {
#pragma unroll
                for (int h = 0; h < 4; h++) {
                    float t = sis[rr][h] + sjl[h];
                    v += fmaxf(t, 0.01f * t);
                }
            }
            amean[rr][tid + 1] = v;
        }
        if (tid < 10) { amean[tid][0] = 0.f; amean[tid][513] = 0.f; }
    }
    __syncthreads();

    int n = r0 + rt;
    if (n >= NF) return;

    int h0 = slot * 2;
    float si0 = sis[rt + 1][h0], si1 = sis[rt + 1][h0 + 1];
    const float* wh0 = &w0s[h0 * 9];
    const float* wh1 = &w0s[(h0 + 1) * 9];
    const float* ccp = (const float*)g_cc + ((size_t)n * NF) * 4 + slot * 2;  // + m*4

    float e0[16], e1[16];
    float sum0 = 0.f, sum1 = 0.f;
#pragma unroll
    for (int c = 0; c < 4; c++) {
        int m4 = c * 128 + lane * 4;     // 4 consecutive output cols m4..m4+3
        // stencil taps for outputs m4..m4+3: amean[rr][m4 .. m4+5] (col shift baked in)
        float4 a0a = *(const float4*)&amean[rt][m4];
        float2 a0b = *(const float2*)&amean[rt][m4 + 4];
        float4 a1a = *(const float4*)&amean[rt + 1][m4];
        float2 a1b = *(const float2*)&amean[rt + 1][m4 + 4];
        float4 a2a = *(const float4*)&amean[rt + 2][m4];
        float2 a2b = *(const float2*)&amean[rt + 2][m4 + 4];
        float t0[6] = {a0a.x, a0a.y, a0a.z, a0a.w, a0b.x, a0b.y};
        float t1[6] = {a1a.x, a1a.y, a1a.z, a1a.w, a1b.x, a1b.y};
        float t2[6] = {a2a.x, a2a.y, a2a.z, a2a.w, a2b.x, a2b.y};
        float4 sj0v = *(const float4*)&sjs[h0][m4];
        float4 sj1v = *(const float4*)&sjs[h0 + 1][m4];
        float sj0a[4] = {sj0v.x, sj0v.y, sj0v.z, sj0v.w};
        float sj1a[4] = {sj1v.x, sj1v.y, sj1v.z, sj1v.w};
#pragma unroll
        for (int j = 0; j < 4; j++) {
            int m = m4 + j;
            bool mval = m < NF;
            float2 cc = make_float2(0.f, 0.f);
            if (mval) cc = *(const float2*)&ccp[(size_t)m * 4];
            float a0 = cc.x, a1 = cc.y;
            a0 = fmaf(wh0[0], t0[j], a0); a0 = fmaf(wh0[1], t0[j+1], a0); a0 = fmaf(wh0[2], t0[j+2], a0);
            a0 = fmaf(wh0[3], t1[j], a0); a0 = fmaf(wh0[4], t1[j+1], a0); a0 = fmaf(wh0[5], t1[j+2], a0);
            a0 = fmaf(wh0[6], t2[j], a0); a0 = fmaf(wh0[7], t2[j+1], a0); a0 = fmaf(wh0[8], t2[j+2], a0);
            a1 = fmaf(wh1[0], t0[j], a1); a1 = fmaf(wh1[1], t0[j+1], a1); a1 = fmaf(wh1[2], t0[j+2], a1);
            a1 = fmaf(wh1[3], t1[j], a1); a1 = fmaf(wh1[4], t1[j+1], a1); a1 = fmaf(wh1[5], t1[j+2], a1);
            a1 = fmaf(wh1[6], t2[j], a1); a1 = fmaf(wh1[7], t2[j+1], a1); a1 = fmaf(wh1[8], t2[j+2], a1);
            float tt0 = si0 + sj0a[j];
            float tt1 = si1 + sj1a[j];
            float lg0 = fmaf(0.1f, fmaxf(tt0, 0.01f * tt0), a0);
            float lg1 = fmaf(0.1f, fmaxf(tt1, 0.01f * tt1), a1);
            e0[c * 4 + j] = mval ? __expf(lg0) : 0.f;  // logits bounded far below exp overflow
            e1[c * 4 + j] = mval ? __expf(lg1) : 0.f;
            sum0 += e0[c * 4 + j]; sum1 += e1[c * 4 + j];
        }
    }
#pragma unroll
    for (int o = 16; o; o >>= 1) {
        sum0 += __shfl_xor_sync(0xffffffffu, sum0, o);
        sum1 += __shfl_xor_sync(0xffffffffu, sum1, o);
    }
    float i0 = 1.0f / sum0, i1 = 1.0f / sum1;
    size_t base0 = ((size_t)(b * 4 + h0) * NF + n) * NF;
    size_t base1 = base0 + (size_t)NF * NF;
    // scalar stores: NF=510 row pitch breaks 16B alignment for STG.128
#pragma unroll
    for (int c = 0; c < 4; c++) {
        int m4 = c * 128 + lane * 4;
#pragma unroll
        for (int j = 0; j < 4; j++) {
            int m = m4 + j;
            if (m < NF) {
                Aout[base0 + m] = e0[c * 4 + j] * i0;
                Aout[base1 + m] = e1[c * 4 + j] * i1;
            }
        }
    }
}

// ---------------- K4: per-head partial = A_h @ xt_h  (R15 proven: FFMA2 + true double buffer) -----
// tile 128x64, 8x8 microtile; ONE __syncthreads per k-tile. grid (4,32,4) = 512 blocks, 128 thr.
__global__ __launch_bounds__(128) void k_av(const float* __restrict__ A) {
    __shared__ __align__(16) float As[2][16 * 132];   // [k][row], pitch 132
    __shared__ __align__(16) float Bs[2][16 * 68];    // [k][col], pitch 68
    int b = blockIdx.y;
    int h = blockIdx.z;
    int r0 = blockIdx.x * 128;
    int nvalid = NF - r0; if (nvalid > 128) nvalid = 128;
    int tid = threadIdx.x;
    int tx = tid & 7, ty = tid >> 3;
    int la_k = tid & 15, la_r0 = (tid >> 4) * 16;
    int lb_c = tid & 63, lb_k0 = (tid >> 6) * 8;

    const float* Ab = A + ((size_t)(b * 4 + h) * NF + r0) * NF;
    const float* Xb = g_xt + (size_t)b * NF * 256 + h * 64;

    unsigned long long acc2[4][8];
#pragma unroll
    for (int i = 0; i < 4; i++)
#pragma unroll
        for (int j = 0; j < 8; j++) acc2[i][j] = 0ull;

    float ra[16], rb[8];
#pragma unroll
    for (int i = 0; i < 16; i++) {
        int row = la_r0 + i;
        ra[i] = (row < nvalid) ? Ab[(size_t)row * NF + la_k] : 0.f;
    }
#pragma unroll
    for (int i = 0; i < 8; i++)
        rb[i] = Xb[(size_t)(lb_k0 + i) * 256 + lb_c];

    int p = 0;
    int ty8 = ty * 8, tx8 = tx * 8;
    for (int it = 0; it < 32; it++) {
        float* asp = As[p];
        float* bsp = Bs[p];
#pragma unroll
        for (int i = 0; i < 16; i++) asp[la_k * 132 + la_r0 + i] = ra[i];
#pragma unroll
        for (int i = 0; i < 8; i++) bsp[(lb_k0 + i) * 68 + lb_c] = rb[i];
        __syncthreads();
        if (it + 1 < 32) {
            int k0 = (it + 1) * 16;
#pragma unroll
            for (int i = 0; i < 16; i++) {
                int row = la_r0 + i;
                ra[i] = (row < nvalid && k0 + la_k < NF) ? Ab[(size_t)row * NF + k0 + la_k] : 0.f;
            }
#pragma unroll
            for (int i = 0; i < 8; i++) {
                int k = k0 + lb_k0 + i;
                rb[i] = (k < NF) ? Xb[(size_t)k * 256 + lb_c] : 0.f;
            }
        }
#pragma unroll
        for (int kk = 0; kk < 16; kk++) {
            ulonglong2 aA = *(const ulonglong2*)&asp[kk * 132 + ty8];      // rows 0-1, 2-3
            ulonglong2 aB = *(const ulonglong2*)&asp[kk * 132 + ty8 + 4];  // rows 4-5, 6-7
            float4 bv0 = *(const float4*)&bsp[kk * 68 + tx8];
            float4 bv1 = *(const float4*)&bsp[kk * 68 + tx8 + 4];
            unsigned long long bp[8] = {pk2(bv0.x), pk2(bv0.y), pk2(bv0.z), pk2(bv0.w),
                                        pk2(bv1.x), pk2(bv1.y), pk2(bv1.z), pk2(bv1.w)};
#pragma unroll
            for (int c = 0; c < 8; c++) {
                ffma2(acc2[0][c], aA.x, bp[c]);
                ffma2(acc2[1][c], aA.y, bp[c]);
                ffma2(acc2[2][c], aB.x, bp[c]);
                ffma2(acc2[3][c], aB.y, bp[c]);
            }
        }
        p ^= 1;
    }
    float* outp = g_outp[h];
#pragma unroll
    for (int j = 0; j < 4; j++) {
        union { unsigned long long u; float2 f; } cc[8];
#pragma unroll
        for (int c = 0; c < 8; c++) cc[c].u = acc2[j][c];
        int row0 = ty * 8 + 2 * j;
        if (row0 < nvalid) {
            size_t base = ((size_t)(b * NF) + r0 + row0) * 64 + tx * 8;
            *(float4*)&outp[base]     = make_float4(cc[0].f.x, cc[1].f.x, cc[2].f.x, cc[3].f.x);
            *(float4*)&outp[base + 4] = make_float4(cc[4].f.x, cc[5].f.x, cc[6].f.x, cc[7].f.x);
        }
        if (row0 + 1 < nvalid) {
            size_t base = ((size_t)(b * NF) + r0 + row0 + 1) * 64 + tx * 8;
            *(float4*)&outp[base]     = make_float4(cc[0].f.y, cc[1].f.y, cc[2].f.y, cc[3].f.y);
            *(float4*)&outp[base + 4] = make_float4(cc[4].f.y, cc[5].f.y, cc[6].f.y, cc[7].f.y);
        }
    }
}

// ---------------- K5: GLU + residual + LayerNorm; 64 rows/block, fws staged once ----------------
__global__ __launch_bounds__(256) void k_fin(const float* __restrict__ x,
                                             const float* __restrict__ fw,
                                             const float* __restrict__ fb,
                                             const float* __restrict__ lng,
                                             const float* __restrict__ lnb,
                                             float* __restrict__ y) {
    __shared__ __align__(16) float fws[64 * 128];   // 32 KB: full fcg_w
    __shared__ float outs[8][64];
    int tid = threadIdx.x;
    {
        const float4* fw4 = (const float4*)fw;
        float4* fs4 = (float4*)fws;
#pragma unroll
        for (int i = 0; i < 8; i++) fs4[tid + i * 256] = fw4[tid + i * 256];
    }
    int w = tid >> 5, lane = tid & 31;
    float fb_a0 = fb[lane], fb_a1 = fb[lane + 32], fb_b0 = fb[64 + lane], fb_b1 = fb[96 + lane];
    float lg0 = lng[lane], lg1 = lng[lane + 32], lb0 = lnb[lane], lb1 = lnb[lane + 32];

    for (int g = 0; g < 8; g++) {
        int r0 = blockIdx.x * 64 + g * 8;
        __syncthreads();   // first iter: covers fws load; later: protects outs reuse
#pragma unroll
        for (int i = 0; i < 2; i++) {
            int idx = tid + i * 256;
            size_t gg = (size_t)r0 * 64 + idx;
            outs[idx >> 6][idx & 63] = 0.25f * (g_outp[0][gg] + g_outp[1][gg] + g_outp[2][gg] + g_outp[3][gg]);
        }
        __syncthreads();
        int row = r0 + w;
        const float* o = outs[w];
        float a0 = fb_a0, a1 = fb_a1, b0 = fb_b0, b1 = fb_b1;
#pragma unroll 4
        for (int k = 0; k < 64; k++) {
            float xo = o[k];
            const float* wr = fws + k * 128;
            a0 = fmaf(xo, wr[lane], a0);
            a1 = fmaf(xo, wr[lane + 32], a1);
            b0 = fmaf(xo, wr[64 + lane], b0);
            b1 = fmaf(xo, wr[96 + lane], b1);
        }
        float g0 = a0 / (1.f + __expf(-b0));
        float g1 = a1 / (1.f + __expf(-b1));
        float y0 = g0 + x[(size_t)row * 64 + lane];
        float y1 = g1 + x[(size_t)row * 64 + lane + 32];
        float s1 = y0 + y1, s2 = y0 * y0 + y1 * y1;
#pragma unroll
        for (int off = 16; off; off >>= 1) {
            s1 += __shfl_xor_sync(0xffffffffu, s1, off);
            s2 += __shfl_xor_sync(0xffffffffu, s2, off);
        }
        float mu = s1 * (1.f / 64.f);
        float var = s2 * (1.f / 64.f) - mu * mu;
        float inv = rsqrtf(var + 1e-5f);
        y[(size_t)row * 64 + lane]      = (y0 - mu) * inv * lg0 + lb0;
        y[(size_t)row * 64 + lane + 32] = (y1 - mu) * inv * lg1 + lb1;
    }
}

extern "C" void kernel_launch(void* const* d_in, const int* in_sizes, int n_in,
                              void* d_out, int out_size) {
    const float* x      = (const float*)d_in[0];
    const float* causal = (const float*)d_in[1];
    const float* W      = (const float*)d_in[2];
    const float* attw   = (const float*)d_in[3];
    const float* cw     = (const float*)d_in[4];
    const float* cb     = (const float*)d_in[5];
    const float* fcgw   = (const float*)d_in[6];
    const float* fcgb   = (const float*)d_in[7];
    const float* lng    = (const float*)d_in[8];
    const float* lnb    = (const float*)d_in[9];

    float* y = (float*)d_out;                       // y: B*N*D
    float* A = y + (size_t)BB * NF * DD;            // A: B*H*N*N

    k_xt  <<<1020, 256>>>(x, W);
    k_s   <<<2040, 256>>>(attw);
    k_cc  <<<510, 512>>>(causal, cw, cb);
    k_attn<<<dim3(64, 32), 512>>>(cw, A);
    k_av  <<<dim3(4, 32, 4), 128>>>(A);
    k_fin <<<255, 256>>>(x, fcgw, fcgb, lng, lnb, y);
}

// round 17
// speedup vs baseline: 1.1761x; 1.1761x over previous
#include <cuda_runtime.h>
#include <cstddef>

#define NF 510
#define BB 32
#define HH 4
#define DD 64

// ---------------- scratch (__device__ globals; no allocation allowed) ----------------
__device__ float  g_xt[(size_t)BB*NF*256];        // xt[b][n][h*64+d]
__device__ float  g_si[BB*HH*NF];                 // s_i[b][h][n]
__device__ float  g_sj[BB*HH*NF];                 // s_j[b][h][n]
__device__ float4 g_cc[(size_t)NF*NF];            // 0.9*(conv3x3(causal, w[:,1]) + bias)
__device__ float  g_outp[4][(size_t)BB*NF*DD];    // per-head partial A_h @ xt_h

// ---- packed f32x2 helpers (FFMA2: 2 MACs / instruction) ----
__device__ __forceinline__ unsigned long long pk2(float v) {
    unsigned long long r;
    unsigned u = __float_as_uint(v);
    asm("mov.b64 %0, {%1, %1};" : "=l"(r) : "r"(u));
    return r;
}
__device__ __forceinline__ void ffma2(unsigned long long& d, unsigned long long a, unsigned long long b) {
    asm("fma.rn.f32x2 %0, %1, %2, %0;" : "+l"(d) : "l"(a), "l"(b));
}

// ---------------- K1: xt = x @ W  + fused s_i/s_j epilogue ----------------
// block = 16 rows x 256 cols; thread c owns col c (head h = c>>6, d = c&63).
__global__ __launch_bounds__(256) void k_xt(const float* __restrict__ x,
                                            const float* __restrict__ W,
                                            const float* __restrict__ attw) {
    __shared__ __align__(16) float xs[16][64];
    __shared__ float red[8][16][2];   // per warp: per row, (si, sj) partial
    int c = threadIdx.x;
    size_t base = (size_t)blockIdx.x * (16 * 64);
#pragma unroll
    for (int i = 0; i < 4; i++) {
        int idx = c + i * 256;
        xs[idx >> 6][idx & 63] = x[base + idx];
    }
    __syncthreads();
    float acc[16];
#pragma unroll
    for (int r = 0; r < 16; r++) acc[r] = 0.f;
    for (int kc = 0; kc < 16; kc++) {
        float w0 = W[(kc * 4 + 0) * 256 + c];
        float w1 = W[(kc * 4 + 1) * 256 + c];
        float w2 = W[(kc * 4 + 2) * 256 + c];
        float w3 = W[(kc * 4 + 3) * 256 + c];
#pragma unroll
        for (int r = 0; r < 16; r++) {
            float4 xv = *(const float4*)&xs[r][kc * 4];
            acc[r] = fmaf(xv.x, w0, acc[r]);
            acc[r] = fmaf(xv.y, w1, acc[r]);
            acc[r] = fmaf(xv.z, w2, acc[r]);
            acc[r] = fmaf(xv.w, w3, acc[r]);
        }
    }
    size_t ob = (size_t)blockIdx.x * (16 * 256);
#pragma unroll
    for (int r = 0; r < 16; r++) g_xt[ob + r * 256 + c] = acc[r];

    // ---- fused s_i / s_j: head h cols live in warps 2h, 2h+1 ----
    int wid = c >> 5, lane = c & 31;
    int h = c >> 6, d = c & 63;
    float aw1 = attw[h * 128 + d];        // attention_w[h, :64]  -> s_i
    float aw2 = attw[h * 128 + 64 + d];   // attention_w[h, 64:]  -> s_j
#pragma unroll
    for (int r = 0; r < 16; r++) {
        float pi = acc[r] * aw1;
        float pj = acc[r] * aw2;
#pragma unroll
        for (int o = 16; o; o >>= 1) {
            pi += __shfl_xor_sync(0xffffffffu, pi, o);
            pj += __shfl_xor_sync(0xffffffffu, pj, o);
        }
        if (!lane) { red[wid][r][0] = pi; red[wid][r][1] = pj; }
    }
    __syncthreads();
    if (c < 64) {
        int r = c >> 2, h2 = c & 3;
        int row = blockIdx.x * 16 + r;
        int b = row / NF, n = row - b * NF;
        float si = red[2 * h2][r][0] + red[2 * h2 + 1][r][0];
        float sj = red[2 * h2][r][1] + red[2 * h2 + 1][r][1];
        g_si[(b * 4 + h2) * NF + n] = si;
        g_sj[(b * 4 + h2) * NF + n] = sj;
    }
}

// ---------------- K2b: Cc = 0.9*(conv3x3(causal, w[:,1,:,:]) + bias), batch-invariant ----------------
__global__ __launch_bounds__(512) void k_cc(const float* __restrict__ causal,
                                            const float* __restrict__ cw,
                                            const float* __restrict__ cb) {
    __shared__ float cs[3][512];
    __shared__ float w1s[36];
    __shared__ float cbs[4];
    int m = threadIdx.x, n = blockIdx.x;
    if (m < 36) w1s[m] = 0.9f * cw[(m / 9) * 18 + 9 + (m % 9)];
    if (m < 4)  cbs[m] = 0.9f * cb[m];
#pragma unroll
    for (int ky = 0; ky < 3; ky++) {
        int rr = n + ky - 1;
        if (m < NF) cs[ky][m + 1] = (rr >= 0 && rr < NF) ? causal[rr * NF + m] : 0.f;
        else        cs[ky][m == NF ? 0 : 511] = 0.f;
    }
    __syncthreads();
    if (m < NF) {
        float c[9];
#pragma unroll
        for (int ky = 0; ky < 3; ky++)
#pragma unroll
            for (int kx = 0; kx < 3; kx++) c[ky * 3 + kx] = cs[ky][m + kx];
        float o[4];
#pragma unroll
        for (int h = 0; h < 4; h++) {
            float v = cbs[h];
#pragma unroll
            for (int j = 0; j < 9; j++) v = fmaf(w1s[h * 9 + j], c[j], v);
            o[h] = v;
        }
        g_cc[n * NF + m] = make_float4(o[0], o[1], o[2], o[3]);
    }
}

// ---------------- K3: warp-pair-per-row, e in registers, A written ONCE (R15-proven form) ----------
// block = 512 thr = 16 warps = 8 rows x 2 head-slots.
__global__ __launch_bounds__(512, 2) void k_attn(const float* __restrict__ cw,
                                                 float* __restrict__ Aout) {
    __shared__ float amean[10][520];   // conv input rows r0-1 .. r0+8; col = m+1
    __shared__ float sjs[4][512];      // s_j per head (cols 510,511 = 0)
    __shared__ float sis[10][4];       // s_i rows r0-1 .. r0+8
    __shared__ float w0s[36];

    int tid = threadIdx.x;
    int b = blockIdx.y;
    int r0 = blockIdx.x * 8;
    int wid = tid >> 5, lane = tid & 31;
    int rt = wid >> 1;                 // row in tile 0..7
    int slot = wid & 1;                // head pair

#pragma unroll
    for (int h = 0; h < 4; h++)
        sjs[h][tid] = (tid < NF) ? g_sj[(b * 4 + h) * NF + tid] : 0.f;
    if (tid < 40) {
        int rr = tid >> 2, h = tid & 3;
        int row = r0 - 1 + rr;
        sis[rr][h] = ((unsigned)row < NF) ? g_si[(b * 4 + h) * NF + row] : 0.f;
    }
    if (tid < 36) w0s[tid] = 0.225f * cw[(tid / 9) * 18 + (tid % 9)];  // 0.9*0.25 folded
    __syncthreads();

    {
        float sjl[4];
#pragma unroll
        for (int h = 0; h < 4; h++) sjl[h] = sjs[h][tid];
        bool mok = tid < NF;
#pragma unroll
        for (int rr = 0; rr < 10; rr++) {
            int row = r0 - 1 + rr;
            float v = 0.f;
            if (mok && (unsigned)row < NF) {
#pragma unroll
                for (int h = 0; h < 4; h++) {
                    float t = sis[rr][h] + sjl[h];
                    v += fmaxf(t, 0.01f * t);
                }
            }
            amean[rr][tid + 1] = v;
        }
        if (tid < 10) { amean[tid][0] = 0.f; amean[tid][513] = 0.f; }
    }
    __syncthreads();

    int n = r0 + rt;
    if (n >= NF) return;

    int h0 = slot * 2;
    float si0 = sis[rt + 1][h0], si1 = sis[rt + 1][h0 + 1];
    const float* wh0 = &w0s[h0 * 9];
    const float* wh1 = &w0s[(h0 + 1) * 9];
    const float* ccp = (const float*)g_cc + ((size_t)n * NF) * 4 + slot * 2;  // + m*4

    float e0[16], e1[16];
    float sum0 = 0.f, sum1 = 0.f;
#pragma unroll
    for (int c = 0; c < 16; c++) {
        int m = c * 32 + lane;
        bool mval = m < NF;
        float t00 = amean[rt][m],     t01 = amean[rt][m + 1],     t02 = amean[rt][m + 2];
        float t10 = amean[rt + 1][m], t11 = amean[rt + 1][m + 1], t12 = amean[rt + 1][m + 2];
        float t20 = amean[rt + 2][m], t21 = amean[rt + 2][m + 1], t22 = amean[rt + 2][m + 2];
        float2 cc = make_float2(0.f, 0.f);
        if (mval) cc = *(const float2*)&ccp[(size_t)m * 4];
        float a0 = cc.x, a1 = cc.y;
        a0 = fmaf(wh0[0], t00, a0); a0 = fmaf(wh0[1], t01, a0); a0 = fmaf(wh0[2], t02, a0);
        a0 = fmaf(wh0[3], t10, a0); a0 = fmaf(wh0[4], t11, a0); a0 = fmaf(wh0[5], t12, a0);
        a0 = fmaf(wh0[6], t20, a0); a0 = fmaf(wh0[7], t21, a0); a0 = fmaf(wh0[8], t22, a0);
        a1 = fmaf(wh1[0], t00, a1); a1 = fmaf(wh1[1], t01, a1); a1 = fmaf(wh1[2], t02, a1);
        a1 = fmaf(wh1[3], t10, a1); a1 = fmaf(wh1[4], t11, a1); a1 = fmaf(wh1[5], t12, a1);
        a1 = fmaf(wh1[6], t20, a1); a1 = fmaf(wh1[7], t21, a1); a1 = fmaf(wh1[8], t22, a1);
        float tt0 = si0 + sjs[h0][m];
        float tt1 = si1 + sjs[h0 + 1][m];
        float lg0 = fmaf(0.1f, fmaxf(tt0, 0.01f * tt0), a0);
        float lg1 = fmaf(0.1f, fmaxf(tt1, 0.01f * tt1), a1);
        e0[c] = mval ? __expf(lg0) : 0.f;   // logits bounded far below fp32 exp overflow
        e1[c] = mval ? __expf(lg1) : 0.f;
        sum0 += e0[c]; sum1 += e1[c];
    }
#pragma unroll
    for (int o = 16; o; o >>= 1) {
        sum0 += __shfl_xor_sync(0xffffffffu, sum0, o);
        sum1 += __shfl_xor_sync(0xffffffffu, sum1, o);
    }
    float i0 = 1.0f / sum0, i1 = 1.0f / sum1;
    size_t base0 = ((size_t)(b * 4 + h0) * NF + n) * NF;
    size_t base1 = base0 + (size_t)NF * NF;
#pragma unroll
    for (int c = 0; c < 16; c++) {
        int m = c * 32 + lane;
        if (m < NF) {
            Aout[base0 + m] = e0[c] * i0;
            Aout[base1 + m] = e1[c] * i1;
        }
    }
}

// ---------------- K4: per-head partial = A_h @ xt_h  (R15-proven: FFMA2 + true double buffer) -----
// tile 128x64, 8x8 microtile; ONE __syncthreads per k-tile. grid (4,32,4) = 512 blocks, 128 thr.
__global__ __launch_bounds__(128) void k_av(const float* __restrict__ A) {
    __shared__ __align__(16) float As[2][16 * 132];   // [k][row], pitch 132
    __shared__ __align__(16) float Bs[2][16 * 68];    // [k][col], pitch 68
    int b = blockIdx.y;
    int h = blockIdx.z;
    int r0 = blockIdx.x * 128;
    int nvalid = NF - r0; if (nvalid > 128) nvalid = 128;
    int tid = threadIdx.x;
    int tx = tid & 7, ty = tid >> 3;
    int la_k = tid & 15, la_r0 = (tid >> 4) * 16;
    int lb_c = tid & 63, lb_k0 = (tid >> 6) * 8;

    const float* Ab = A + ((size_t)(b * 4 + h) * NF + r0) * NF;
    const float* Xb = g_xt + (size_t)b * NF * 256 + h * 64;

    unsigned long long acc2[4][8];
#pragma unroll
    for (int i = 0; i < 4; i++)
#pragma unroll
        for (int j = 0; j < 8; j++) acc2[i][j] = 0ull;

    float ra[16], rb[8];
#pragma unroll
    for (int i = 0; i < 16; i++) {
        int row = la_r0 + i;
        ra[i] = (row < nvalid) ? Ab[(size_t)row * NF + la_k] : 0.f;
    }
#pragma unroll
    for (int i = 0; i < 8; i++)
        rb[i] = Xb[(size_t)(lb_k0 + i) * 256 + lb_c];

    int p = 0;
    int ty8 = ty * 8, tx8 = tx * 8;
    for (int it = 0; it < 32; it++) {
        float* asp = As[p];
        float* bsp = Bs[p];
#pragma unroll
        for (int i = 0; i < 16; i++) asp[la_k * 132 + la_r0 + i] = ra[i];
#pragma unroll
        for (int i = 0; i < 8; i++) bsp[(lb_k0 + i) * 68 + lb_c] = rb[i];
        __syncthreads();
        if (it + 1 < 32) {
            int k0 = (it + 1) * 16;
#pragma unroll
            for (int i = 0; i < 16; i++) {
                int row = la_r0 + i;
                ra[i] = (row < nvalid && k0 + la_k < NF) ? Ab[(size_t)row * NF + k0 + la_k] : 0.f;
            }
#pragma unroll
            for (int i = 0; i < 8; i++) {
                int k = k0 + lb_k0 + i;
                rb[i] = (k < NF) ? Xb[(size_t)k * 256 + lb_c] : 0.f;
            }
        }
#pragma unroll
        for (int kk = 0; kk < 16; kk++) {
            ulonglong2 aA = *(const ulonglong2*)&asp[kk * 132 + ty8];      // rows 0-1, 2-3
            ulonglong2 aB = *(const ulonglong2*)&asp[kk * 132 + ty8 + 4];  // rows 4-5, 6-7
            float4 bv0 = *(const float4*)&bsp[kk * 68 + tx8];
            float4 bv1 = *(const float4*)&bsp[kk * 68 + tx8 + 4];
            unsigned long long bp[8] = {pk2(bv0.x), pk2(bv0.y), pk2(bv0.z), pk2(bv0.w),
                                        pk2(bv1.x), pk2(bv1.y), pk2(bv1.z), pk2(bv1.w)};
#pragma unroll
            for (int c = 0; c < 8; c++) {
                ffma2(acc2[0][c], aA.x, bp[c]);
                ffma2(acc2[1][c], aA.y, bp[c]);
                ffma2(acc2[2][c], aB.x, bp[c]);
                ffma2(acc2[3][c], aB.y, bp[c]);
            }
        }
        p ^= 1;
    }
    float* outp = g_outp[h];
#pragma unroll
    for (int j = 0; j < 4; j++) {
        union { unsigned long long u; float2 f; } cc[8];
#pragma unroll
        for (int c = 0; c < 8; c++) cc[c].u = acc2[j][c];
        int row0 = ty * 8 + 2 * j;
        if (row0 < nvalid) {
            size_t base = ((size_t)(b * NF) + r0 + row0) * 64 + tx * 8;
            *(float4*)&outp[base]     = make_float4(cc[0].f.x, cc[1].f.x, cc[2].f.x, cc[3].f.x);
            *(float4*)&outp[base + 4] = make_float4(cc[4].f.x, cc[5].f.x, cc[6].f.x, cc[7].f.x);
        }
        if (row0 + 1 < nvalid) {
            size_t base = ((size_t)(b * NF) + r0 + row0 + 1) * 64 + tx * 8;
            *(float4*)&outp[base]     = make_float4(cc[0].f.y, cc[1].f.y, cc[2].f.y, cc[3].f.y);
            *(float4*)&outp[base + 4] = make_float4(cc[4].f.y, cc[5].f.y, cc[6].f.y, cc[7].f.y);
        }
    }
}

// ---------------- K5: GLU + residual + LayerNorm; 64 rows/block, fws staged once ----------------
__global__ __launch_bounds__(256) void k_fin(const float* __restrict__ x,
                                             const float* __restrict__ fw,
                                             const float* __restrict__ fb,
                                             const float* __restrict__ lng,
                                             const float* __restrict__ lnb,
                                             float* __restrict__ y) {
    __shared__ __align__(16) float fws[64 * 128];   // 32 KB: full fcg_w
    __shared__ float outs[8][64];
    int tid = threadIdx.x;
    {
        const float4* fw4 = (const float4*)fw;
        float4* fs4 = (float4*)fws;
#pragma unroll
        for (int i = 0; i < 8; i++) fs4[tid + i * 256] = fw4[tid + i * 256];
    }
    int w = tid >> 5, lane = tid & 31;
    float fb_a0 = fb[lane], fb_a1 = fb[lane + 32], fb_b0 = fb[64 + lane], fb_b1 = fb[96 + lane];
    float lg0 = lng[lane], lg1 = lng[lane + 32], lb0 = lnb[lane], lb1 = lnb[lane + 32];

    for (int g = 0; g < 8; g++) {
        int r0 = blockIdx.x * 64 + g * 8;
        __syncthreads();   // first iter: covers fws load; later: protects outs reuse
#pragma unroll
        for (int i = 0; i < 2; i++) {
            int idx = tid + i * 256;
            size_t gg = (size_t)r0 * 64 + idx;
            outs[idx >> 6][idx & 63] = 0.25f * (g_outp[0][gg] + g_outp[1][gg] + g_outp[2][gg] + g_outp[3][gg]);
        }
        __syncthreads();
        int row = r0 + w;
        const float* o = outs[w];
        float a0 = fb_a0, a1 = fb_a1, b0 = fb_b0, b1 = fb_b1;
#pragma unroll 4
        for (int k = 0; k < 64; k++) {
            float xo = o[k];
            const float* wr = fws + k * 128;
            a0 = fmaf(xo, wr[lane], a0);
            a1 = fmaf(xo, wr[lane + 32], a1);
            b0 = fmaf(xo, wr[64 + lane], b0);
            b1 = fmaf(xo, wr[96 + lane], b1);
        }
        float g0 = a0 / (1.f + __expf(-b0));
        float g1 = a1 / (1.f + __expf(-b1));
        float y0 = g0 + x[(size_t)row * 64 + lane];
        float y1 = g1 + x[(size_t)row * 64 + lane + 32];
        float s1 = y0 + y1, s2 = y0 * y0 + y1 * y1;
#pragma unroll
        for (int off = 16; off; off >>= 1) {
            s1 += __shfl_xor_sync(0xffffffffu, s1, off);
            s2 += __shfl_xor_sync(0xffffffffu, s2, off);
        }
        float mu = s1 * (1.f / 64.f);
        float var = s2 * (1.f / 64.f) - mu * mu;
        float inv = rsqrtf(var + 1e-5f);
        y[(size_t)row * 64 + lane]      = (y0 - mu) * inv * lg0 + lb0;
        y[(size_t)row * 64 + lane + 32] = (y1 - mu) * inv * lg1 + lb1;
    }
}

extern "C" void kernel_launch(void* const* d_in, const int* in_sizes, int n_in,
                              void* d_out, int out_size) {
    const float* x      = (const float*)d_in[0];
    const float* causal = (const float*)d_in[1];
    const float* W      = (const float*)d_in[2];
    const float* attw   = (const float*)d_in[3];
    const float* cw     = (const float*)d_in[4];
    const float* cb     = (const float*)d_in[5];
    const float* fcgw   = (const float*)d_in[6];
    const float* fcgb   = (const float*)d_in[7];
    const float* lng    = (const float*)d_in[8];
    const float* lnb    = (const float*)d_in[9];

    float* y = (float*)d_out;                       // y: B*N*D
    float* A = y + (size_t)BB * NF * DD;            // A: B*H*N*N

    k_xt  <<<1020, 256>>>(x, W, attw);
    k_cc  <<<510, 512>>>(causal, cw, cb);
    k_attn<<<dim3(64, 32), 512>>>(cw, A);
    k_av  <<<dim3(4, 32, 4), 128>>>(A);
    k_fin <<<255, 256>>>(x, fcgw, fcgb, lng, lnb, y);
}